// round 17
// baseline (speedup 1.0000x reference)
#include <cuda_runtime.h>
#include <cuda_fp16.h>
#include <cstdint>

// ---------------------------------------------------------------------------
// IntentSlotLabellingModel on GB300 (sm_103a), Round 16:
// R15 base (231.9us) + memory-parallel L3:
//  * L3 was latency-bound (2.05 TB/s achieved, DRAM 23%, 256 CTAs). New
//    L3 kernel: CTA tile 64x128 -> 512 CTAs, warp tile 32x32, occ 2 —
//    double the outstanding cp.async streams, Z still read exactly once.
//  * L1 (occ-2 fused gather), L2, prep, PDL: byte-identical to R15.
//   M=32768, E=512, C=512, H=1024, L=128.
// ---------------------------------------------------------------------------

#define BM 128
#define BN 128
#define BK 64
#define DEPTH 3
#define SSTR_H 72                       // padded row stride in halves (144 B)
#define A_STH (BM * SSTR_H)             // 9216 halves / stage
#define B_STH (BN * SSTR_H)             // 9216 halves / stage
#define STG_H (A_STH + B_STH)           // 18432 halves / stage
#define SMEM_BYTES (DEPTH * STG_H * 2)  // 110592 B -> 2 CTAs/SM

// L3 geometry: CTA 64x128
#define L3_A_STH (64 * SSTR_H)          // 4608 halves / stage
#define L3_STG_H (L3_A_STH + B_STH)     // 13824 halves / stage
#define L3_SMEM (DEPTH * L3_STG_H * 2)  // 82944 B -> 2 CTAs/SM

__device__ __half g_H[32768L * 512];    // post-conv relu (fp16)
__device__ __half g_Z[32768L * 1024];   // post-dec1 relu (fp16)
__device__ __half g_cw[512L * 512];     // conv_w  fp16 [N,K]
__device__ __half g_w1t[1024L * 512];   // dec_w1 -> fp16 [N,K]
__device__ __half g_w2t[128L * 1024];   // dec_w2 -> fp16 [N,K]

__device__ __forceinline__ uint32_t smem_u32(const void* p) {
    uint32_t a;
    asm("{ .reg .u64 t; cvta.to.shared.u64 t, %1; cvt.u32.u64 %0, t; }"
        : "=r"(a) : "l"(p));
    return a;
}
__device__ __forceinline__ void cp_async16(uint32_t dst, const void* src) {
    asm volatile("cp.async.cg.shared.global [%0], [%1], 16;"
                 :: "r"(dst), "l"(src) : "memory");
}
__device__ __forceinline__ void cp_commit() {
    asm volatile("cp.async.commit_group;" ::: "memory");
}
template <int N> __device__ __forceinline__ void cp_wait() {
    asm volatile("cp.async.wait_group %0;" :: "n"(N) : "memory");
}
__device__ __forceinline__ void pdl_trigger() {
    asm volatile("griddepcontrol.launch_dependents;" ::: "memory");
}
__device__ __forceinline__ void pdl_wait() {
    asm volatile("griddepcontrol.wait;" ::: "memory");
}
__device__ __forceinline__ void mma_f16(float* d, const uint32_t* a, const uint32_t* b) {
    asm volatile(
        "mma.sync.aligned.m16n8k16.row.col.f32.f16.f16.f32 "
        "{%0,%1,%2,%3}, {%4,%5,%6,%7}, {%8,%9}, {%0,%1,%2,%3};"
        : "+f"(d[0]), "+f"(d[1]), "+f"(d[2]), "+f"(d[3])
        : "r"(a[0]), "r"(a[1]), "r"(a[2]), "r"(a[3]), "r"(b[0]), "r"(b[1]));
}

// ---------------------------------------------------------------------------
// Weight prep: w1/w2 transpose + conv_w cvt, 896 blocks.
// ---------------------------------------------------------------------------
__device__ __forceinline__ void tile_transpose_cvt(
    const float* __restrict__ in, __half* __restrict__ out,
    int K, int N, int bx, int by, int tid)
{
    __shared__ float t[32][33];
    int n0 = bx * 32, k0 = by * 32;
    int x = tid & 31, y = tid >> 5;
    #pragma unroll
    for (int i = 0; i < 32; i += 8)
        t[y + i][x] = in[(long)(k0 + y + i) * N + n0 + x];
    __syncthreads();
    #pragma unroll
    for (int i = 0; i < 32; i += 8)
        out[(long)(n0 + y + i) * K + k0 + x] = __float2half_rn(t[x][y + i]);
}

__global__ void prep_weights(const float* __restrict__ w1, __half* __restrict__ w1t,
                             const float* __restrict__ w2, __half* __restrict__ w2t,
                             const float* __restrict__ cw, __half* __restrict__ cwh)
{
    pdl_trigger();
    const int b = blockIdx.x;
    const int tid = threadIdx.x;
    if (b < 512) {
        tile_transpose_cvt(w1, w1t, 512, 1024, b & 31, b >> 5, tid);
    } else if (b < 640) {
        int bb = b - 512;
        tile_transpose_cvt(w2, w2t, 1024, 128, bb & 3, bb >> 2, tid);
    } else {
        long i = ((long)(b - 640) * 256 + tid) * 4;
        const float4 v = *reinterpret_cast<const float4*>(cw + i);
        *reinterpret_cast<__half2*>(cwh + i)     = __floats2half2_rn(v.x, v.y);
        *reinterpret_cast<__half2*>(cwh + i + 2) = __floats2half2_rn(v.z, v.w);
    }
}

// ---------------------------------------------------------------------------
// L1 fused kernel, occ 2 (R15 proven): H = relu(emb[tok] @ CW^T + bias)
// ---------------------------------------------------------------------------
__global__ void __launch_bounds__(256, 2)
mma_gemm_l1(const float* __restrict__ emb, const int* __restrict__ tokens,
            const __half* __restrict__ B, const float* __restrict__ bias,
            __half* __restrict__ C, int N, int K)
{
    extern __shared__ __half smem[];
    const uint32_t sbase = smem_u32(smem);

    const int tid  = threadIdx.x;
    const int lane = tid & 31;
    const int warp = tid >> 5;
    const int warp_m = (warp >> 2) * 64;
    const int warp_n = (warp & 3) * 32;
    const int gr = lane >> 2;
    const int gc = lane & 3;

    const int  n0 = blockIdx.x * BN;
    const long m0 = (long)blockIdx.y * BM;

    const int r_base = tid >> 4;
    const int c4     = (tid & 15) * 4;
    const float* a_src[8]; int a_soff[8];
    #pragma unroll
    for (int i = 0; i < 8; i++) {
        int r = r_base + i * 16;
        a_src[i]  = emb + (long)tokens[m0 + r] * 512 + c4;
        a_soff[i] = r * SSTR_H + c4;
    }
    const int rb0 = tid >> 3;
    const int c8  = (tid & 7) * 8;
    const __half* b_base = B + (long)(n0 + rb0) * (long)K + c8;
    const uint32_t b_dst0 = sbase + (uint32_t)(A_STH + rb0 * SSTR_H + c8) * 2u;
    const long  bg_step = 32L * K;
    const uint32_t bs_step = 32u * SSTR_H * 2u;

    const int S = K / BK;

    auto issueB = [&](int s) {
        const uint32_t so = (uint32_t)((s % DEPTH) * STG_H * 2);
        const int k0 = s * BK;
        #pragma unroll
        for (int i = 0; i < 4; i++)
            cp_async16(b_dst0 + so + i * bs_step, b_base + k0 + i * bg_step);
    };

    float4 ra[4];
    auto loadA4 = [&](int s, int h) {
        const int k0 = s * BK;
        #pragma unroll
        for (int i = 0; i < 4; i++)
            ra[i] = *reinterpret_cast<const float4*>(a_src[h * 4 + i] + k0);
    };
    auto stsA4 = [&](int s, int h) {
        __half* As = smem + (s % DEPTH) * STG_H;
        #pragma unroll
        for (int i = 0; i < 4; i++) {
            __half2 h0 = __floats2half2_rn(ra[i].x, ra[i].y);
            __half2 h1 = __floats2half2_rn(ra[i].z, ra[i].w);
            uint2 u;
            u.x = *reinterpret_cast<uint32_t*>(&h0);
            u.y = *reinterpret_cast<uint32_t*>(&h1);
            *reinterpret_cast<uint2*>(&smem[(s % DEPTH) * STG_H + a_soff[h * 4 + i]]) = u;
            (void)As;
        }
    };

    loadA4(0, 0); stsA4(0, 0);
    loadA4(0, 1); stsA4(0, 1);
    pdl_wait();
    issueB(0); cp_commit();
    issueB(1); cp_commit();

    float acc[4][4][4];
    #pragma unroll
    for (int mt = 0; mt < 4; mt++)
        #pragma unroll
        for (int nt = 0; nt < 4; nt++)
            #pragma unroll
            for (int r = 0; r < 4; r++)
                acc[mt][nt][r] = 0.0f;

    for (int s = 0; s < S; s++) {
        if (s + 1 < S) loadA4(s + 1, 0);
        cp_wait<DEPTH - 2>();
        __syncthreads();
        if (s + 2 < S) { issueB(s + 2); cp_commit(); }

        const __half* As = smem + (s % DEPTH) * STG_H;
        const __half* Bs = As + A_STH;

        #pragma unroll
        for (int ks = 0; ks < BK; ks += 16) {
            uint32_t af[4][4], bf[4][2];
            #pragma unroll
            for (int mt = 0; mt < 4; mt++) {
                int r = (warp_m + mt * 16 + gr) * SSTR_H + ks + gc * 2;
                af[mt][0] = *reinterpret_cast<const uint32_t*>(&As[r]);
                af[mt][1] = *reinterpret_cast<const uint32_t*>(&As[r + 8 * SSTR_H]);
                af[mt][2] = *reinterpret_cast<const uint32_t*>(&As[r + 8]);
                af[mt][3] = *reinterpret_cast<const uint32_t*>(&As[r + 8 * SSTR_H + 8]);
            }
            #pragma unroll
            for (int nt = 0; nt < 4; nt++) {
                int r = (warp_n + nt * 8 + gr) * SSTR_H + ks + gc * 2;
                bf[nt][0] = *reinterpret_cast<const uint32_t*>(&Bs[r]);
                bf[nt][1] = *reinterpret_cast<const uint32_t*>(&Bs[r + 8]);
            }
            #pragma unroll
            for (int mt = 0; mt < 4; mt++)
                #pragma unroll
                for (int nt = 0; nt < 4; nt++)
                    mma_f16(acc[mt][nt], af[mt], bf[nt]);

            if (ks == 16 && s + 1 < S) {
                stsA4(s + 1, 0);
                loadA4(s + 1, 1);
            }
        }

        if (s + 1 < S) stsA4(s + 1, 1);
    }

    pdl_trigger();

    #pragma unroll
    for (int nt = 0; nt < 4; nt++) {
        int n = n0 + warp_n + nt * 8 + gc * 2;
        float bb0 = bias[n], bb1 = bias[n + 1];
        #pragma unroll
        for (int mt = 0; mt < 4; mt++) {
            long m = m0 + warp_m + mt * 16 + gr;
            __half2 h0 = __floats2half2_rn(fmaxf(acc[mt][nt][0] + bb0, 0.0f),
                                           fmaxf(acc[mt][nt][1] + bb1, 0.0f));
            __half2 h1 = __floats2half2_rn(fmaxf(acc[mt][nt][2] + bb0, 0.0f),
                                           fmaxf(acc[mt][nt][3] + bb1, 0.0f));
            *reinterpret_cast<__half2*>(C + m * (long)N + n)       = h0;
            *reinterpret_cast<__half2*>(C + (m + 8) * (long)N + n) = h1;
        }
    }
}

// ---------------------------------------------------------------------------
// L2 GEMM (proven mainloop, PDL): Z = relu(H @ W1T^T + b1), half out
// ---------------------------------------------------------------------------
__global__ void __launch_bounds__(256, 2)
mma_gemm_l2(const __half* __restrict__ A, const __half* __restrict__ B,
            const float* __restrict__ bias, __half* __restrict__ C,
            int N, int K)
{
    extern __shared__ __half smem[];
    const uint32_t sbase = smem_u32(smem);

    const int tid  = threadIdx.x;
    const int lane = tid & 31;
    const int warp = tid >> 5;
    const int warp_m = (warp >> 2) * 64;
    const int warp_n = (warp & 3) * 32;
    const int gr = lane >> 2;
    const int gc = lane & 3;

    const int  n0 = blockIdx.x * BN;
    const long m0 = (long)blockIdx.y * BM;

    const int r0 = tid >> 3;
    const int c8 = (tid & 7) * 8;
    const __half* a_base = A + (m0 + r0) * (long)K + c8;
    const __half* b_base = B + (long)(n0 + r0) * (long)K + c8;
    const uint32_t a_dst0 = sbase + (uint32_t)(r0 * SSTR_H + c8) * 2u;
    const uint32_t b_dst0 = sbase + (uint32_t)(A_STH + r0 * SSTR_H + c8) * 2u;
    const long  g_step = 32L * K;
    const uint32_t s_step = 32u * SSTR_H * 2u;

    const int S = K / BK;

    auto issueA = [&](int s) {
        const uint32_t so = (uint32_t)((s % DEPTH) * STG_H * 2);
        const int k0 = s * BK;
        #pragma unroll
        for (int i = 0; i < 4; i++)
            cp_async16(a_dst0 + so + i * s_step, a_base + k0 + i * g_step);
    };
    auto issueB = [&](int s) {
        const uint32_t so = (uint32_t)((s % DEPTH) * STG_H * 2);
        const int k0 = s * BK;
        #pragma unroll
        for (int i = 0; i < 4; i++)
            cp_async16(b_dst0 + so + i * s_step, b_base + k0 + i * g_step);
    };

    issueB(0); issueB(1);
    pdl_wait();
    issueA(0); cp_commit();
    issueA(1); cp_commit();

    float acc[4][4][4];
    #pragma unroll
    for (int mt = 0; mt < 4; mt++)
        #pragma unroll
        for (int nt = 0; nt < 4; nt++)
            #pragma unroll
            for (int r = 0; r < 4; r++)
                acc[mt][nt][r] = 0.0f;

    for (int s = 0; s < S; s++) {
        cp_wait<DEPTH - 2>();
        __syncthreads();
        if (s + 2 < S) { issueA(s + 2); issueB(s + 2); }
        cp_commit();

        const __half* As = smem + (s % DEPTH) * STG_H;
        const __half* Bs = As + A_STH;

        #pragma unroll
        for (int ks = 0; ks < BK; ks += 16) {
            uint32_t af[4][4], bf[4][2];
            #pragma unroll
            for (int mt = 0; mt < 4; mt++) {
                int r = (warp_m + mt * 16 + gr) * SSTR_H + ks + gc * 2;
                af[mt][0] = *reinterpret_cast<const uint32_t*>(&As[r]);
                af[mt][1] = *reinterpret_cast<const uint32_t*>(&As[r + 8 * SSTR_H]);
                af[mt][2] = *reinterpret_cast<const uint32_t*>(&As[r + 8]);
                af[mt][3] = *reinterpret_cast<const uint32_t*>(&As[r + 8 * SSTR_H + 8]);
            }
            #pragma unroll
            for (int nt = 0; nt < 4; nt++) {
                int r = (warp_n + nt * 8 + gr) * SSTR_H + ks + gc * 2;
                bf[nt][0] = *reinterpret_cast<const uint32_t*>(&Bs[r]);
                bf[nt][1] = *reinterpret_cast<const uint32_t*>(&Bs[r + 8]);
            }
            #pragma unroll
            for (int mt = 0; mt < 4; mt++)
                #pragma unroll
                for (int nt = 0; nt < 4; nt++)
                    mma_f16(acc[mt][nt], af[mt], bf[nt]);
        }
    }

    pdl_trigger();

    #pragma unroll
    for (int nt = 0; nt < 4; nt++) {
        int n = n0 + warp_n + nt * 8 + gc * 2;
        float bb0 = bias[n], bb1 = bias[n + 1];
        #pragma unroll
        for (int mt = 0; mt < 4; mt++) {
            long m = m0 + warp_m + mt * 16 + gr;
            __half2 h0 = __floats2half2_rn(fmaxf(acc[mt][nt][0] + bb0, 0.0f),
                                           fmaxf(acc[mt][nt][1] + bb1, 0.0f));
            __half2 h1 = __floats2half2_rn(fmaxf(acc[mt][nt][2] + bb0, 0.0f),
                                           fmaxf(acc[mt][nt][3] + bb1, 0.0f));
            *reinterpret_cast<__half2*>(C + m * (long)N + n)       = h0;
            *reinterpret_cast<__half2*>(C + (m + 8) * (long)N + n) = h1;
        }
    }
}

// ---------------------------------------------------------------------------
// L3 GEMM, memory-parallel: out[64x128 tile] = Z @ W2T^T + b2 (float out)
// CTA 64x128 -> 512 CTAs; 8 warps 2m x 4n, warp tile 32x32 (acc 32 regs).
// ---------------------------------------------------------------------------
__global__ void __launch_bounds__(256, 2)
mma_gemm_l3(const __half* __restrict__ A, const __half* __restrict__ B,
            const float* __restrict__ bias, float* __restrict__ C,
            int N, int K)
{
    extern __shared__ __half smem[];
    const uint32_t sbase = smem_u32(smem);

    const int tid  = threadIdx.x;
    const int lane = tid & 31;
    const int warp = tid >> 5;
    const int warp_m = (warp >> 2) * 32;     // 0,32
    const int warp_n = (warp & 3) * 32;      // 0,32,64,96
    const int gr = lane >> 2;
    const int gc = lane & 3;

    const int  n0 = 0;                        // grid.x == 1 (N = 128 = BN)
    const long m0 = (long)blockIdx.y * 64;

    // A producer: 64 rows x 64 halves / stage = 512 cp16 -> 2 per thread
    const int ra0 = tid >> 3;                 // 0..31
    const int c8  = (tid & 7) * 8;
    const __half* a_base = A + (m0 + ra0) * (long)K + c8;
    const uint32_t a_dst0 = sbase + (uint32_t)(ra0 * SSTR_H + c8) * 2u;
    // B producer: 128 rows -> 1024 cp16 -> 4 per thread
    const __half* b_base = B + (long)(n0 + ra0) * (long)K + c8;
    const uint32_t b_dst0 = sbase + (uint32_t)(L3_A_STH + ra0 * SSTR_H + c8) * 2u;
    const long  g_step = 32L * K;
    const uint32_t s_step = 32u * SSTR_H * 2u;

    const int S = K / BK;                     // 16

    auto issueA = [&](int s) {
        const uint32_t so = (uint32_t)((s % DEPTH) * L3_STG_H * 2);
        const int k0 = s * BK;
        #pragma unroll
        for (int i = 0; i < 2; i++)
            cp_async16(a_dst0 + so + i * s_step, a_base + k0 + i * g_step);
    };
    auto issueB = [&](int s) {
        const uint32_t so = (uint32_t)((s % DEPTH) * L3_STG_H * 2);
        const int k0 = s * BK;
        #pragma unroll
        for (int i = 0; i < 4; i++)
            cp_async16(b_dst0 + so + i * s_step, b_base + k0 + i * g_step);
    };

    issueB(0); issueB(1);                     // weights: no dependency
    pdl_wait();
    issueA(0); cp_commit();
    issueA(1); cp_commit();

    float acc[2][4][4];
    #pragma unroll
    for (int mt = 0; mt < 2; mt++)
        #pragma unroll
        for (int nt = 0; nt < 4; nt++)
            #pragma unroll
            for (int r = 0; r < 4; r++)
                acc[mt][nt][r] = 0.0f;

    for (int s = 0; s < S; s++) {
        cp_wait<DEPTH - 2>();
        __syncthreads();
        if (s + 2 < S) { issueA(s + 2); issueB(s + 2); }
        cp_commit();

        const __half* As = smem + (s % DEPTH) * L3_STG_H;
        const __half* Bs = As + L3_A_STH;

        #pragma unroll
        for (int ks = 0; ks < BK; ks += 16) {
            uint32_t af[2][4], bf[4][2];
            #pragma unroll
            for (int mt = 0; mt < 2; mt++) {
                int r = (warp_m + mt * 16 + gr) * SSTR_H + ks + gc * 2;
                af[mt][0] = *reinterpret_cast<const uint32_t*>(&As[r]);
                af[mt][1] = *reinterpret_cast<const uint32_t*>(&As[r + 8 * SSTR_H]);
                af[mt][2] = *reinterpret_cast<const uint32_t*>(&As[r + 8]);
                af[mt][3] = *reinterpret_cast<const uint32_t*>(&As[r + 8 * SSTR_H + 8]);
            }
            #pragma unroll
            for (int nt = 0; nt < 4; nt++) {
                int r = (warp_n + nt * 8 + gr) * SSTR_H + ks + gc * 2;
                bf[nt][0] = *reinterpret_cast<const uint32_t*>(&Bs[r]);
                bf[nt][1] = *reinterpret_cast<const uint32_t*>(&Bs[r + 8]);
            }
            #pragma unroll
            for (int mt = 0; mt < 2; mt++)
                #pragma unroll
                for (int nt = 0; nt < 4; nt++)
                    mma_f16(acc[mt][nt], af[mt], bf[nt]);
        }
    }

    #pragma unroll
    for (int nt = 0; nt < 4; nt++) {
        int n = n0 + warp_n + nt * 8 + gc * 2;
        float bb0 = bias[n], bb1 = bias[n + 1];
        #pragma unroll
        for (int mt = 0; mt < 2; mt++) {
            long m = m0 + warp_m + mt * 16 + gr;
            *reinterpret_cast<float2*>(C + m * (long)N + n) =
                make_float2(acc[mt][nt][0] + bb0, acc[mt][nt][1] + bb1);
            *reinterpret_cast<float2*>(C + (m + 8) * (long)N + n) =
                make_float2(acc[mt][nt][2] + bb0, acc[mt][nt][3] + bb1);
        }
    }
}

extern "C" void kernel_launch(void* const* d_in, const int* in_sizes, int n_in,
                              void* d_out, int out_size)
{
    const int*   tokens = (const int*)  d_in[0];
    const float* emb    = (const float*)d_in[1];
    const float* conv_w = (const float*)d_in[2];
    const float* conv_b = (const float*)d_in[3];
    const float* w1     = (const float*)d_in[4];
    const float* b1     = (const float*)d_in[5];
    const float* w2     = (const float*)d_in[6];
    const float* b2     = (const float*)d_in[7];
    float* out = (float*)d_out;

    const int M = in_sizes[0];   // 32768

    __half *H, *Z, *CW, *W1T, *W2T;
    cudaGetSymbolAddress((void**)&H,   g_H);
    cudaGetSymbolAddress((void**)&Z,   g_Z);
    cudaGetSymbolAddress((void**)&CW,  g_cw);
    cudaGetSymbolAddress((void**)&W1T, g_w1t);
    cudaGetSymbolAddress((void**)&W2T, g_w2t);

    cudaFuncSetAttribute(mma_gemm_l1,
                         cudaFuncAttributeMaxDynamicSharedMemorySize, SMEM_BYTES);
    cudaFuncSetAttribute(mma_gemm_l2,
                         cudaFuncAttributeMaxDynamicSharedMemorySize, SMEM_BYTES);
    cudaFuncSetAttribute(mma_gemm_l3,
                         cudaFuncAttributeMaxDynamicSharedMemorySize, L3_SMEM);

    const int MB = M / BM;   // 256

    prep_weights<<<896, 256>>>(w1, W1T, w2, W2T, conv_w, CW);

    cudaLaunchAttribute attrs[1];
    attrs[0].id = cudaLaunchAttributeProgrammaticStreamSerialization;
    attrs[0].val.programmaticStreamSerializationAllowed = 1;

    // L1: H = half(relu(emb[tok] @ CW^T + conv_b))        [M, 512]
    {
        cudaLaunchConfig_t cfg = {};
        cfg.gridDim = dim3(512 / BN, MB);
        cfg.blockDim = dim3(256);
        cfg.dynamicSmemBytes = SMEM_BYTES;
        cfg.attrs = attrs; cfg.numAttrs = 1;
        cudaLaunchKernelEx(&cfg, mma_gemm_l1,
                           emb, tokens, (const __half*)CW, conv_b, H, 512, 512);
    }
    // L2: Z = half(relu(H @ W1T^T + b1))                  [M, 1024]
    {
        cudaLaunchConfig_t cfg = {};
        cfg.gridDim = dim3(1024 / BN, MB);
        cfg.blockDim = dim3(256);
        cfg.dynamicSmemBytes = SMEM_BYTES;
        cfg.attrs = attrs; cfg.numAttrs = 1;
        cudaLaunchKernelEx(&cfg, mma_gemm_l2,
                           (const __half*)H, (const __half*)W1T, b1, Z,
                           1024, 512);
    }
    // L3: out = Z @ W2T^T + b2                            [M, 128]
    {
        cudaLaunchConfig_t cfg = {};
        cfg.gridDim = dim3(1, M / 64);       // 512 CTAs
        cfg.blockDim = dim3(256);
        cfg.dynamicSmemBytes = L3_SMEM;
        cfg.attrs = attrs; cfg.numAttrs = 1;
        cudaLaunchKernelEx(&cfg, mma_gemm_l3,
                           (const __half*)Z, (const __half*)W2T, b2, out,
                           128, 1024);
    }
}